// round 9
// baseline (speedup 1.0000x reference)
#include <cuda_runtime.h>
#include <cstdint>

typedef long long ll;
typedef unsigned long long ull;

#define MAXM 204800
#define INF  0x7FFFFFFF
#define CN   100      // tour length
#define CEM  128      // embedding dim

// succ[g]  = global node id following g in its instance's tour
// slot[g]  = {min fwd edge idx for edge (g,succ[g]), min rev edge idx} packed
__device__ int  g_succ[MAXM];
__device__ int2 g_slot[MAXM];

// Identify which of the two small buffers is y (the other is arange node_offset).
__device__ __forceinline__ const int* pick_y(const void* candA, const void* candB) {
    const ll*  a64 = (const ll*)candA;
    const int* a32 = (const int*)candA;
    bool arange = (a64[1] == 1 && a64[2] == 2 && a64[3] == 3 && a64[4] == 4) ||
                  (a32[1] == 1 && a32[2] == 2 && a32[3] == 3 && a32[4] == 4);
    return (const int*)(arange ? candB : candA);
}

// ---------------- prep: init slots + build successor array ------------------
__global__ void prep_kernel(const void* candA, const void* candB, int M, int N) {
    __shared__ const int* ysh;
    if (threadIdx.x == 0) ysh = pick_y(candA, candB);
    __syncthreads();
    const int* y = ysh;

    const int t = blockIdx.x * blockDim.x + threadIdx.x;
    if (t >= M) return;

    // vectorized INF init (8B store per node)
    ((ull*)g_slot)[t] = 0x7FFFFFFF7FFFFFFFull;

    const int i    = t % N;
    const int base = t - i;                    // row*N
    const int yt   = y[t];

    // y[t+1] from the next lane when it's in the same row; else load.
    const int lane = threadIdx.x & 31;
    int ynext = __shfl_down_sync(0xFFFFFFFFu, yt, 1);
    if (lane == 31 || i + 1 == N) {
        const int j = (i + 1 == N) ? 0 : i + 1;
        ynext = y[base + j];
    }
    g_succ[base + yt] = base + ynext;
}

// ---------------- insert: classify each edge against the tours --------------
__global__ void insert_kernel(const void* ei_v, int E) {
    __shared__ int is64sh;
    if (threadIdx.x == 0) {
        const ll* e64 = (const ll*)ei_v;
        bool is64 = true;
        #pragma unroll
        for (int k = 0; k < 4; ++k)
            if (e64[k] < 0 || e64[k] >= (1ll << 32)) is64 = false;
        is64sh = is64 ? 1 : 0;
    }
    __syncthreads();

    const int i = blockIdx.x * blockDim.x + threadIdx.x;
    if (i >= E) return;
    int s, d;
    if (is64sh) {
        const ll* e = (const ll*)ei_v;
        s = (int)e[i]; d = (int)e[E + i];
    } else {
        const int* e = (const int*)ei_v;
        s = e[i]; d = e[E + i];
    }
    if (g_succ[s] == d) atomicMin(&g_slot[s].x, i);   // forward tour edge
    if (g_succ[d] == s) atomicMin(&g_slot[d].y, i);   // reverse tour edge
}

// ---------------- gather+mean: one block per (s,b) row ----------------------
// The tour edges of row r are exactly {(g, succ[g]) : g in [base, base+N)} and
// the mean is order-invariant, so phase 1 is a COALESCED int2 read of
// g_slot[base+tid] — no y reads, no random lookups.
// Phase 2: 4 warps; warp g accumulates rows g, g+4, ... as float4 (one full
// 512B row per warp iteration, fully unrolled -> deep MLP), then a 4-way
// smem reduction.
__global__ void __launch_bounds__(CEM)
gather_mean_kernel(const float4* __restrict__ emb, float* __restrict__ out) {
    __shared__ int    s_idx[CN];
    __shared__ float4 s_part[4][CEM / 4];
    const int row = blockIdx.x;
    const int tid = threadIdx.x;

    if (tid < CN) {
        const int2 fr = g_slot[row * CN + tid];
        const int  m  = (fr.x != INF) ? fr.x : fr.y;
        s_idx[tid] = (m != INF) ? m : -1;
    }
    __syncthreads();

    const int g = tid >> 5, lane = tid & 31;
    float4 acc = make_float4(0.f, 0.f, 0.f, 0.f);
    #pragma unroll
    for (int i = g; i < CN; i += 4) {           // 25 fully-unrolled iterations
        const int idx = s_idx[i];
        if (idx >= 0) {
            const float4 v = emb[(size_t)idx * (CEM / 4) + lane];
            acc.x += v.x; acc.y += v.y; acc.z += v.z; acc.w += v.w;
        }
    }
    s_part[g][lane] = acc;
    __syncthreads();

    const float* p = (const float*)s_part;      // [4][CEM] floats
    const float  s = p[tid] + p[CEM + tid] + p[2 * CEM + tid] + p[3 * CEM + tid];
    out[(size_t)row * CEM + tid] = s * (1.0f / (float)CN);
}

// ---------------- Launcher ---------------------------------------------------
extern "C" void kernel_launch(void* const* d_in, const int* in_sizes, int n_in,
                              void* d_out, int out_size) {
    // Bind inputs by element count (order-independent):
    //   edge_emb 52,428,800 | edge_index 819,200 | y / node_offset 204,800 each
    int iemb = 0;
    for (int i = 1; i < n_in; ++i) if (in_sizes[i] > in_sizes[iemb]) iemb = i;
    int iei = -1;
    for (int i = 0; i < n_in; ++i)
        if (i != iemb && (iei < 0 || in_sizes[i] > in_sizes[iei])) iei = i;
    int ia = -1, ib = -1;
    for (int i = 0; i < n_in; ++i)
        if (i != iemb && i != iei) { if (ia < 0) ia = i; else ib = i; }

    const void*   candA    = d_in[ia];
    const void*   candB    = d_in[ib];
    const void*   edge_idx = d_in[iei];
    const float4* edge_emb = (const float4*)d_in[iemb];
    float*        out      = (float*)d_out;

    int M = in_sizes[ia];              // 204800 = S*B*N
    if (M > MAXM) M = MAXM;
    const int E  = in_sizes[iei] / 2;  // 409600
    const int SB = M / CN;             // 2048

    prep_kernel  <<<(M + 255) / 256, 256>>>(candA, candB, M, CN);
    insert_kernel<<<(E + 255) / 256, 256>>>(edge_idx, E);
    gather_mean_kernel<<<SB, CEM>>>(edge_emb, out);
}

// round 12
// speedup vs baseline: 1.0094x; 1.0094x over previous
#include <cuda_runtime.h>
#include <cstdint>

typedef long long ll;
typedef unsigned long long ull;

#define MAXM 204800
#define INF  0x7FFFFFFF
#define CN   100      // tour length
#define CEM  128      // embedding dim

// succ[g]  = global node id following g in its instance's tour
// slot[g]  = {min fwd edge idx for edge (g,succ[g]), min rev edge idx}
__device__ int  g_succ[MAXM];
__device__ int2 g_slot[MAXM];

// Identify which of the two small buffers is y (the other is arange node_offset).
__device__ __forceinline__ const int* pick_y(const void* candA, const void* candB) {
    const ll*  a64 = (const ll*)candA;
    const int* a32 = (const int*)candA;
    bool arange = (a64[1] == 1 && a64[2] == 2 && a64[3] == 3 && a64[4] == 4) ||
                  (a32[1] == 1 && a32[2] == 2 && a32[3] == 3 && a32[4] == 4);
    return (const int*)(arange ? candB : candA);
}

// ---------------- prep: init slots + build successor array ------------------
// 4 nodes per thread: int4 y load, 2x int4 INF store, 4 succ stores.
// i = t4 % 100 is a multiple of 4, so i+k (k<4) never crosses the row;
// the wrap happens only at i==96,k==3.
__global__ void prep_kernel(const void* candA, const void* candB, int M) {
    __shared__ const int* ysh;
    if (threadIdx.x == 0) ysh = pick_y(candA, candB);
    __syncthreads();
    const int* y = ysh;

    const int t4 = (blockIdx.x * blockDim.x + threadIdx.x) * 4;
    if (t4 >= M) return;

    const int4 inf4 = make_int4(INF, INF, INF, INF);
    ((int4*)g_slot)[(t4 >> 1)]     = inf4;      // slots t4, t4+1
    ((int4*)g_slot)[(t4 >> 1) + 1] = inf4;      // slots t4+2, t4+3

    const int4 yv   = ((const int4*)y)[t4 >> 2];
    const int  i    = t4 % CN;
    const int  base = t4 - i;                   // row*CN
    const int  ys0 = yv.x, ys1 = yv.y, ys2 = yv.z, ys3 = yv.w;
    // successor-of-last: wrap to row start if i==96, else y[t4+4]
    const int  ys4 = (i + 4 == CN) ? y[base] : y[t4 + 4];

    g_succ[base + ys0] = base + ys1;
    g_succ[base + ys1] = base + ys2;
    g_succ[base + ys2] = base + ys3;
    g_succ[base + ys3] = base + ys4;
}

// ---------------- insert: classify each edge against the tours --------------
// 2 edges per thread: vector loads of both halves, 4 independent succ probes.
__global__ void insert_kernel(const void* ei_v, int E) {
    __shared__ int is64sh;
    if (threadIdx.x == 0) {
        const ll* e64 = (const ll*)ei_v;
        bool is64 = true;
        #pragma unroll
        for (int k = 0; k < 4; ++k)
            if (e64[k] < 0 || e64[k] >= (1ll << 32)) is64 = false;
        is64sh = is64 ? 1 : 0;
    }
    __syncthreads();

    const int i2 = (blockIdx.x * blockDim.x + threadIdx.x) * 2;
    if (i2 >= E) return;

    int s0, s1, d0, d1;
    if (is64sh) {
        const longlong2 sv = ((const longlong2*)ei_v)[i2 >> 1];
        const longlong2 dv = ((const longlong2*)((const ll*)ei_v + E))[i2 >> 1];
        s0 = (int)sv.x; s1 = (int)sv.y; d0 = (int)dv.x; d1 = (int)dv.y;
    } else {
        const int2 sv = ((const int2*)ei_v)[i2 >> 1];
        const int2 dv = ((const int2*)((const int*)ei_v + E))[i2 >> 1];
        s0 = sv.x; s1 = sv.y; d0 = dv.x; d1 = dv.y;
    }

    const int ss0 = g_succ[s0], ss1 = g_succ[s1];   // 4 independent probes
    const int sd0 = g_succ[d0], sd1 = g_succ[d1];

    if (ss0 == d0) atomicMin(&g_slot[s0].x, i2);
    if (sd0 == s0) atomicMin(&g_slot[d0].y, i2);
    if (ss1 == d1) atomicMin(&g_slot[s1].x, i2 + 1);
    if (sd1 == s1) atomicMin(&g_slot[d1].y, i2 + 1);
}

// ---------------- gather+mean: one block per (s,b) row ----------------------
// (unchanged from the 27.1us kernel) Coalesced int2 slot read, then 4 warps
// accumulate float4 rows (25 fully-unrolled iterations each), 4-way smem
// reduction.
__global__ void __launch_bounds__(CEM)
gather_mean_kernel(const float4* __restrict__ emb, float* __restrict__ out) {
    __shared__ int    s_idx[CN];
    __shared__ float4 s_part[4][CEM / 4];
    const int row = blockIdx.x;
    const int tid = threadIdx.x;

    if (tid < CN) {
        const int2 fr = g_slot[row * CN + tid];
        const int  m  = (fr.x != INF) ? fr.x : fr.y;
        s_idx[tid] = (m != INF) ? m : -1;
    }
    __syncthreads();

    const int g = tid >> 5, lane = tid & 31;
    float4 acc = make_float4(0.f, 0.f, 0.f, 0.f);
    #pragma unroll
    for (int i = g; i < CN; i += 4) {
        const int idx = s_idx[i];
        if (idx >= 0) {
            const float4 v = emb[(size_t)idx * (CEM / 4) + lane];
            acc.x += v.x; acc.y += v.y; acc.z += v.z; acc.w += v.w;
        }
    }
    s_part[g][lane] = acc;
    __syncthreads();

    const float* p = (const float*)s_part;
    const float  s = p[tid] + p[CEM + tid] + p[2 * CEM + tid] + p[3 * CEM + tid];
    out[(size_t)row * CEM + tid] = s * (1.0f / (float)CN);
}

// ---------------- Launcher ---------------------------------------------------
extern "C" void kernel_launch(void* const* d_in, const int* in_sizes, int n_in,
                              void* d_out, int out_size) {
    // Bind inputs by element count (order-independent):
    //   edge_emb 52,428,800 | edge_index 819,200 | y / node_offset 204,800 each
    int iemb = 0;
    for (int i = 1; i < n_in; ++i) if (in_sizes[i] > in_sizes[iemb]) iemb = i;
    int iei = -1;
    for (int i = 0; i < n_in; ++i)
        if (i != iemb && (iei < 0 || in_sizes[i] > in_sizes[iei])) iei = i;
    int ia = -1, ib = -1;
    for (int i = 0; i < n_in; ++i)
        if (i != iemb && i != iei) { if (ia < 0) ia = i; else ib = i; }

    const void*   candA    = d_in[ia];
    const void*   candB    = d_in[ib];
    const void*   edge_idx = d_in[iei];
    const float4* edge_emb = (const float4*)d_in[iemb];
    float*        out      = (float*)d_out;

    int M = in_sizes[ia];              // 204800 = S*B*N
    if (M > MAXM) M = MAXM;
    const int E  = in_sizes[iei] / 2;  // 409600
    const int SB = M / CN;             // 2048

    const int prepT = M / 4;           // 51200 threads
    const int insT  = E / 2;           // 204800 threads
    prep_kernel  <<<(prepT + 255) / 256, 256>>>(candA, candB, M);
    insert_kernel<<<(insT  + 255) / 256, 256>>>(edge_idx, E);
    gather_mean_kernel<<<SB, CEM>>>(edge_emb, out);
}